// round 1
// baseline (speedup 1.0000x reference)
#include <cuda_runtime.h>
#include <math.h>

#define B 16
#define N 512
#define D 768
#define H 12
#define DK 64
#define ND 32
#define ROWS (B * N)          // 8192
#define OUT_ELEMS ((size_t)B * N * D)        // 6291456
#define ATT_ELEMS ((size_t)B * H * N * N)    // 50331648

// ---------------- scratch (static device allocations) ----------------
__device__ float g_x[ROWS * D];    // LayerNorm output
__device__ float g_q[ROWS * D];    // (B,H,N,DK)
__device__ float g_k[ROWS * D];
__device__ float g_v[ROWS * D];
__device__ float g_ao[ROWS * D];   // attention output (B,N,H*DK)
__device__ int g_px[ROWS];
__device__ int g_py[ROWS];
__device__ unsigned char g_bins[B * N * N];

// ---------------- LayerNorm ----------------
__global__ void __launch_bounds__(256) ln_kernel(const float* __restrict__ f,
                                                 const float* __restrict__ gamma,
                                                 const float* __restrict__ beta) {
    int row = blockIdx.x;
    int t = threadIdx.x;
    const float* x = f + (size_t)row * D;
    float v[3];
    float s = 0.f, s2 = 0.f;
#pragma unroll
    for (int i = 0; i < 3; i++) {
        v[i] = x[t + i * 256];
        s += v[i];
        s2 += v[i] * v[i];
    }
    __shared__ float redA[8], redB[8];
#pragma unroll
    for (int o = 16; o; o >>= 1) {
        s += __shfl_xor_sync(~0u, s, o);
        s2 += __shfl_xor_sync(~0u, s2, o);
    }
    if ((t & 31) == 0) { redA[t >> 5] = s; redB[t >> 5] = s2; }
    __syncthreads();
    if (t < 32) {
        float a = (t < 8) ? redA[t] : 0.f;
        float c = (t < 8) ? redB[t] : 0.f;
#pragma unroll
        for (int o = 4; o; o >>= 1) {
            a += __shfl_xor_sync(~0u, a, o);
            c += __shfl_xor_sync(~0u, c, o);
        }
        if (t == 0) { redA[0] = a; redB[0] = c; }
    }
    __syncthreads();
    float mu = redA[0] * (1.0f / D);
    float var = redB[0] * (1.0f / D) - mu * mu;
    float rstd = rsqrtf(var + 1e-5f);
    float* xo = g_x + (size_t)row * D;
#pragma unroll
    for (int i = 0; i < 3; i++) {
        int c = t + i * 256;
        xo[c] = (v[i] - mu) * rstd * gamma[c] + beta[c];
    }
}

// ---------------- patch bins ----------------
__global__ void patch_kernel(const float* __restrict__ boxes,
                             const int* __restrict__ iszs) {
    int idx = blockIdx.x * 256 + threadIdx.x;
    if (idx >= ROWS) return;
    int b = idx >> 9;
    float w = (float)iszs[b * 4 + 0];
    float h = (float)iszs[b * 4 + 1];
    const float* bx = boxes + (size_t)idx * 4;
    float p0 = bx[0] * w, p1 = bx[1] * h, p2 = bx[2] * w, p3 = bx[3] * h;
    float spw = floorf(w / 11.0f);
    float sph = floorf(h / 11.0f);
    float cx = floorf((p0 + p2) * 0.5f);
    float cy = floorf((p1 + p3) * 0.5f);
    int px = 0, py = 0;
    bool fx = false, fy = false;
#pragma unroll
    for (int j = 0; j < 11; j++) {
        float jl = (float)j, jh = (float)(j + 1);
        float lo = jl * spw, hi = jh * spw;
        if (!fx && lo <= cx && cx <= hi) { px = j; fx = true; }
        float lo2 = jl * sph, hi2 = jh * sph;
        if (!fy && lo2 <= cy && cy <= hi2) { py = j; fy = true; }
    }
    g_px[idx] = px;
    g_py[idx] = py;
}

// ---------------- distance bins (B,N,N) uint8 ----------------
__global__ void bins_kernel() {
    int idx = blockIdx.x * 256 + threadIdx.x;   // B*N*N = 4194304
    int j = idx & (N - 1);
    int i = (idx >> 9) & (N - 1);
    int b = idx >> 18;
    float dx = (float)(g_px[b * N + j] - g_px[b * N + i]);
    float dy = (float)(g_py[b * N + j] - g_py[b * N + i]);
    g_bins[idx] = (unsigned char)(int)(sqrtf(dx * dx + dy * dy) * 2.0f);
}

// ---------------- GEMM body: C(8192x768) = A(8192x768) * W(768x768)^T + bias ----------------
__device__ __forceinline__ void gemm_body(const float* __restrict__ A,
                                          const float* __restrict__ W,
                                          const float* __restrict__ bias,
                                          float* __restrict__ out,
                                          bool head_layout) {
    __shared__ float As[16][64];
    __shared__ float Ws[16][64];
    int tid = threadIdx.x;
    int tx = tid & 15, ty = tid >> 4;
    int r0 = blockIdx.y * 64;
    int c0 = blockIdx.x * 64;
    int lr = tid & 63;
    int lk = (tid >> 6) << 2;
    float acc[4][4] = {};
    const float* Ap = A + (size_t)(r0 + lr) * D + lk;
    const float* Wp = W + (size_t)(c0 + lr) * D + lk;
    for (int k0 = 0; k0 < D; k0 += 16) {
        float4 av = *(const float4*)(Ap + k0);
        float4 wv = *(const float4*)(Wp + k0);
        As[lk + 0][lr] = av.x; As[lk + 1][lr] = av.y;
        As[lk + 2][lr] = av.z; As[lk + 3][lr] = av.w;
        Ws[lk + 0][lr] = wv.x; Ws[lk + 1][lr] = wv.y;
        Ws[lk + 2][lr] = wv.z; Ws[lk + 3][lr] = wv.w;
        __syncthreads();
#pragma unroll
        for (int kk = 0; kk < 16; kk++) {
            float4 a = *(const float4*)&As[kk][ty << 2];
            float4 bb = *(const float4*)&Ws[kk][tx << 2];
            float aa[4] = {a.x, a.y, a.z, a.w};
            float bv[4] = {bb.x, bb.y, bb.z, bb.w};
#pragma unroll
            for (int i = 0; i < 4; i++)
#pragma unroll
                for (int j = 0; j < 4; j++) acc[i][j] += aa[i] * bv[j];
        }
        __syncthreads();
    }
    float bs[4];
#pragma unroll
    for (int j = 0; j < 4; j++) bs[j] = bias[c0 + (tx << 2) + j];
#pragma unroll
    for (int i = 0; i < 4; i++) {
        int r = r0 + (ty << 2) + i;
        float4 o = make_float4(acc[i][0] + bs[0], acc[i][1] + bs[1],
                               acc[i][2] + bs[2], acc[i][3] + bs[3]);
        if (head_layout) {
            int b = r >> 9, n = r & 511;
            int hh = c0 >> 6;            // one head per 64-col tile
            int dk = tx << 2;
            *(float4*)&out[(((size_t)(b * H + hh) * N + n) * DK) + dk] = o;
        } else {
            *(float4*)&out[(size_t)r * D + c0 + (tx << 2)] = o;
        }
    }
}

__global__ void __launch_bounds__(256) gemm_qkv(const float* __restrict__ Wq, const float* __restrict__ bq,
                                                const float* __restrict__ Wk, const float* __restrict__ bk,
                                                const float* __restrict__ Wv, const float* __restrict__ bv) {
    const float *Wm, *bias;
    float* out;
    int z = blockIdx.z;
    if (z == 0)      { Wm = Wq; bias = bq; out = g_q; }
    else if (z == 1) { Wm = Wk; bias = bk; out = g_k; }
    else             { Wm = Wv; bias = bv; out = g_v; }
    gemm_body(g_x, Wm, bias, out, true);
}

__global__ void __launch_bounds__(256) gemm_out(const float* __restrict__ Wo,
                                                const float* __restrict__ bo,
                                                float* __restrict__ out) {
    gemm_body(g_ao, Wo, bo, out, false);
}

// ---------------- attention: per (b,h, 32-q-row tile) ----------------
#define QT 32
#define KT 64
#define SMEM_ATTN ((64 * 32 + 64 * 64 + 32 * 512 + 32) * 4)

__global__ void __launch_bounds__(256) attn_kernel(const float* __restrict__ dist_emb,
                                                   float* __restrict__ att_out) {
    extern __shared__ float sm[];
    float* Qs = sm;                 // [d=64][qi=32]
    float* KV = sm + 64 * 32;       // K: [d=64][ki=64] / V: [ki=64][dk=64]
    float* Sc = KV + 64 * 64;       // [32][512]
    float* dh = Sc + 32 * 512;      // [32]

    int tid = threadIdx.x;
    int bh = blockIdx.y;
    int b = bh / H;
    int h = bh - b * H;
    int q0 = blockIdx.x * QT;

    if (tid < ND) dh[tid] = dist_emb[tid * H + h];

    // load Q tile transposed
    {
        int qi = tid >> 3;
        int d0 = (tid & 7) << 3;
        const float* qp = g_q + ((size_t)bh * N + q0 + qi) * DK + d0;
        float4 v0 = *(const float4*)qp;
        float4 v1 = *(const float4*)(qp + 4);
        Qs[(d0 + 0) * 32 + qi] = v0.x; Qs[(d0 + 1) * 32 + qi] = v0.y;
        Qs[(d0 + 2) * 32 + qi] = v0.z; Qs[(d0 + 3) * 32 + qi] = v0.w;
        Qs[(d0 + 4) * 32 + qi] = v1.x; Qs[(d0 + 5) * 32 + qi] = v1.y;
        Qs[(d0 + 6) * 32 + qi] = v1.z; Qs[(d0 + 7) * 32 + qi] = v1.w;
    }
    __syncthreads();

    int tx = tid & 15, ty = tid >> 4;
    const float scale = 0.125f;   // 1/sqrt(64)

    // scores: Sc[qi][k] = (q . k) * scale
    for (int kt = 0; kt < N; kt += KT) {
        int ki = tid >> 2;
        int d0 = (tid & 3) << 4;
        const float* kp = g_k + ((size_t)bh * N + kt + ki) * DK + d0;
#pragma unroll
        for (int t2 = 0; t2 < 4; t2++) {
            float4 v = *(const float4*)(kp + t2 * 4);
            KV[(d0 + t2 * 4 + 0) * 64 + ki] = v.x;
            KV[(d0 + t2 * 4 + 1) * 64 + ki] = v.y;
            KV[(d0 + t2 * 4 + 2) * 64 + ki] = v.z;
            KV[(d0 + t2 * 4 + 3) * 64 + ki] = v.w;
        }
        __syncthreads();
        float acc[2][4] = {};
        int qi2 = ty << 1, ki4 = tx << 2;
#pragma unroll 8
        for (int d = 0; d < DK; d++) {
            float a0 = Qs[d * 32 + qi2];
            float a1 = Qs[d * 32 + qi2 + 1];
            float4 bv = *(const float4*)&KV[d * 64 + ki4];
            acc[0][0] += a0 * bv.x; acc[0][1] += a0 * bv.y;
            acc[0][2] += a0 * bv.z; acc[0][3] += a0 * bv.w;
            acc[1][0] += a1 * bv.x; acc[1][1] += a1 * bv.y;
            acc[1][2] += a1 * bv.z; acc[1][3] += a1 * bv.w;
        }
#pragma unroll
        for (int i = 0; i < 2; i++) {
            *(float4*)&Sc[(qi2 + i) * 512 + kt + ki4] =
                make_float4(acc[i][0] * scale, acc[i][1] * scale,
                            acc[i][2] * scale, acc[i][3] * scale);
        }
        __syncthreads();
    }

    // softmax(+bias) rows, write att
    {
        int w = tid >> 5, lane = tid & 31;
#pragma unroll
        for (int rr = 0; rr < 4; rr++) {
            int qi = w + (rr << 3);
            int qg = q0 + qi;
            const unsigned char* brow = g_bins + ((size_t)b * N + qg) * N;
            float* srow = Sc + qi * 512;
            float m = -1e30f;
            for (int kk = lane; kk < N; kk += 32) {
                float s = srow[kk] + dh[brow[kk]];
                srow[kk] = s;
                m = fmaxf(m, s);
            }
#pragma unroll
            for (int o = 16; o; o >>= 1) m = fmaxf(m, __shfl_xor_sync(~0u, m, o));
            float ssum = 0.f;
            for (int kk = lane; kk < N; kk += 32) {
                float e = __expf(srow[kk] - m);
                srow[kk] = e;
                ssum += e;
            }
#pragma unroll
            for (int o = 16; o; o >>= 1) ssum += __shfl_xor_sync(~0u, ssum, o);
            float inv = 1.0f / ssum;
            float* arow = att_out + ((size_t)bh * N + qg) * N;
            for (int kk = lane; kk < N; kk += 32) {
                float p = srow[kk] * inv;
                srow[kk] = p;
                arow[kk] = p;
            }
        }
    }
    __syncthreads();

    // O = P @ V
    float oacc[2][4] = {};
    int qi2 = ty << 1, dk4 = tx << 2;
    for (int kt = 0; kt < N; kt += KT) {
        int ki = tid >> 2;
        int d0 = (tid & 3) << 4;
        const float* vp = g_v + ((size_t)bh * N + kt + ki) * DK + d0;
#pragma unroll
        for (int t2 = 0; t2 < 4; t2++) {
            *(float4*)&KV[ki * 64 + d0 + t2 * 4] = *(const float4*)(vp + t2 * 4);
        }
        __syncthreads();
#pragma unroll 8
        for (int ki2 = 0; ki2 < KT; ki2++) {
            float a0 = Sc[qi2 * 512 + kt + ki2];
            float a1 = Sc[(qi2 + 1) * 512 + kt + ki2];
            float4 bv = *(const float4*)&KV[ki2 * 64 + dk4];
            oacc[0][0] += a0 * bv.x; oacc[0][1] += a0 * bv.y;
            oacc[0][2] += a0 * bv.z; oacc[0][3] += a0 * bv.w;
            oacc[1][0] += a1 * bv.x; oacc[1][1] += a1 * bv.y;
            oacc[1][2] += a1 * bv.z; oacc[1][3] += a1 * bv.w;
        }
        __syncthreads();
    }
#pragma unroll
    for (int i = 0; i < 2; i++) {
        int qg = q0 + qi2 + i;
        *(float4*)&g_ao[((size_t)b * N + qg) * D + h * DK + dk4] =
            make_float4(oacc[i][0], oacc[i][1], oacc[i][2], oacc[i][3]);
    }
}

// ---------------- launch ----------------
extern "C" void kernel_launch(void* const* d_in, const int* in_sizes, int n_in,
                              void* d_out, int out_size) {
    const float* features = (const float*)d_in[0];
    const float* boxes    = (const float*)d_in[1];
    const int*   iszs     = (const int*)  d_in[2];
    const float* Wq = (const float*)d_in[3];
    const float* bq = (const float*)d_in[4];
    const float* Wk = (const float*)d_in[5];
    const float* bk = (const float*)d_in[6];
    const float* Wv = (const float*)d_in[7];
    const float* bv = (const float*)d_in[8];
    const float* Wo = (const float*)d_in[9];
    const float* bo = (const float*)d_in[10];
    const float* gamma = (const float*)d_in[11];
    const float* beta  = (const float*)d_in[12];
    const float* dist_emb = (const float*)d_in[13];

    float* out = (float*)d_out;
    float* att = ((size_t)out_size >= OUT_ELEMS + ATT_ELEMS) ? out + OUT_ELEMS : out;

    cudaFuncSetAttribute(attn_kernel, cudaFuncAttributeMaxDynamicSharedMemorySize, SMEM_ATTN);

    ln_kernel<<<ROWS, 256>>>(features, gamma, beta);
    patch_kernel<<<(ROWS + 255) / 256, 256>>>(boxes, iszs);
    bins_kernel<<<(B * N * N) / 256, 256>>>();

    dim3 gq(D / 64, ROWS / 64, 3);
    gemm_qkv<<<gq, 256>>>(Wq, bq, Wk, bk, Wv, bv);

    dim3 ga(N / QT, B * H);
    attn_kernel<<<ga, 256, SMEM_ATTN>>>(dist_emb, att);

    dim3 go(D / 64, ROWS / 64);
    gemm_out<<<go, 256>>>(Wo, bo, out);
}

// round 3
// speedup vs baseline: 1.6854x; 1.6854x over previous
#include <cuda_runtime.h>
#include <math.h>
#include <stdint.h>

#define B 16
#define N 512
#define D 768
#define H 12
#define DK 64
#define ND 32
#define ROWS (B * N)          // 8192
#define OUT_ELEMS ((size_t)B * N * D)
#define ATT_ELEMS ((size_t)B * H * N * N)

// ---------------- scratch ----------------
__device__ float g_x[ROWS * D];
__device__ float g_q[ROWS * D];
__device__ float g_k[ROWS * D];
__device__ float g_v[ROWS * D];
__device__ float g_ao[ROWS * D];
__device__ float g_wt[4 * D * D];   // tf32-rounded weights: Wq,Wk,Wv,Wo
__device__ int g_px[ROWS];
__device__ int g_py[ROWS];
__device__ unsigned char g_bins[B * N * N];

__device__ __forceinline__ float to_tf32(float x) {
    uint32_t u;
    asm("cvt.rna.tf32.f32 %0, %1;" : "=r"(u) : "f"(x));
    return __uint_as_float(u);
}
__device__ __forceinline__ uint32_t smem_u32(const void* p) {
    uint32_t a;
    asm("{ .reg .u64 t; cvta.to.shared.u64 t, %1; cvt.u32.u64 %0, t; }" : "=r"(a) : "l"(p));
    return a;
}
#define CP_ASYNC8(dst, src) asm volatile("cp.async.ca.shared.global [%0], [%1], 8;" :: "r"(dst), "l"(src) : "memory")
#define CP_COMMIT()         asm volatile("cp.async.commit_group;" ::: "memory")

__device__ __forceinline__ void mma8(float* d, const uint32_t* a, const uint32_t* b) {
    asm volatile("mma.sync.aligned.m16n8k8.row.col.f32.tf32.tf32.f32 "
                 "{%0,%1,%2,%3}, {%4,%5,%6,%7}, {%8,%9}, {%0,%1,%2,%3};"
                 : "+f"(d[0]), "+f"(d[1]), "+f"(d[2]), "+f"(d[3])
                 : "r"(a[0]), "r"(a[1]), "r"(a[2]), "r"(a[3]), "r"(b[0]), "r"(b[1]));
}

// ---------------- LayerNorm (writes tf32-rounded) ----------------
__global__ void __launch_bounds__(256) ln_kernel(const float* __restrict__ f,
                                                 const float* __restrict__ gamma,
                                                 const float* __restrict__ beta) {
    int row = blockIdx.x;
    int t = threadIdx.x;
    const float* x = f + (size_t)row * D;
    float v[3];
    float s = 0.f, s2 = 0.f;
#pragma unroll
    for (int i = 0; i < 3; i++) {
        v[i] = x[t + i * 256];
        s += v[i];
        s2 += v[i] * v[i];
    }
    __shared__ float redA[8], redB[8];
#pragma unroll
    for (int o = 16; o; o >>= 1) {
        s += __shfl_xor_sync(~0u, s, o);
        s2 += __shfl_xor_sync(~0u, s2, o);
    }
    if ((t & 31) == 0) { redA[t >> 5] = s; redB[t >> 5] = s2; }
    __syncthreads();
    if (t < 32) {
        float a = (t < 8) ? redA[t] : 0.f;
        float c = (t < 8) ? redB[t] : 0.f;
#pragma unroll
        for (int o = 4; o; o >>= 1) {
            a += __shfl_xor_sync(~0u, a, o);
            c += __shfl_xor_sync(~0u, c, o);
        }
        if (t == 0) { redA[0] = a; redB[0] = c; }
    }
    __syncthreads();
    float mu = redA[0] * (1.0f / D);
    float var = redB[0] * (1.0f / D) - mu * mu;
    float rstd = rsqrtf(var + 1e-5f);
    float* xo = g_x + (size_t)row * D;
#pragma unroll
    for (int i = 0; i < 3; i++) {
        int c = t + i * 256;
        xo[c] = to_tf32((v[i] - mu) * rstd * gamma[c] + beta[c]);
    }
}

// ---------------- weight tf32 rounding ----------------
__global__ void __launch_bounds__(256) cvt_w(const float* __restrict__ Wq,
                                             const float* __restrict__ Wk,
                                             const float* __restrict__ Wv,
                                             const float* __restrict__ Wo) {
    int i = blockIdx.x * 256 + threadIdx.x;   // 0 .. D*D-1
    int z = blockIdx.y;
    const float* src = (z == 0) ? Wq : (z == 1) ? Wk : (z == 2) ? Wv : Wo;
    g_wt[(size_t)z * D * D + i] = to_tf32(src[i]);
}

// ---------------- patch bins ----------------
__global__ void patch_kernel(const float* __restrict__ boxes,
                             const int* __restrict__ iszs) {
    int idx = blockIdx.x * 256 + threadIdx.x;
    if (idx >= ROWS) return;
    int b = idx >> 9;
    float w = (float)iszs[b * 4 + 0];
    float h = (float)iszs[b * 4 + 1];
    const float* bx = boxes + (size_t)idx * 4;
    float p0 = bx[0] * w, p1 = bx[1] * h, p2 = bx[2] * w, p3 = bx[3] * h;
    float spw = floorf(w / 11.0f);
    float sph = floorf(h / 11.0f);
    float cx = floorf((p0 + p2) * 0.5f);
    float cy = floorf((p1 + p3) * 0.5f);
    int px = 0, py = 0;
    bool fx = false, fy = false;
#pragma unroll
    for (int j = 0; j < 11; j++) {
        float jl = (float)j, jh = (float)(j + 1);
        float lo = jl * spw, hi = jh * spw;
        if (!fx && lo <= cx && cx <= hi) { px = j; fx = true; }
        float lo2 = jl * sph, hi2 = jh * sph;
        if (!fy && lo2 <= cy && cy <= hi2) { py = j; fy = true; }
    }
    g_px[idx] = px;
    g_py[idx] = py;
}

__global__ void bins_kernel() {
    int idx = blockIdx.x * 256 + threadIdx.x;
    int j = idx & (N - 1);
    int i = (idx >> 9) & (N - 1);
    int b = idx >> 18;
    float dx = (float)(g_px[b * N + j] - g_px[b * N + i]);
    float dy = (float)(g_py[b * N + j] - g_py[b * N + i]);
    g_bins[idx] = (unsigned char)(int)(sqrtf(dx * dx + dy * dy) * 2.0f);
}

// ================ mma.sync tf32 GEMM: C[8192,768] = A @ W^T + bias ================
#define BM 128
#define BN 128
#define BK 32
#define PADK 36                      // smem row stride (floats)
#define MATF (BM * PADK)             // 4608 floats per matrix per stage
#define SSTRIDE (2 * MATF)           // 9216 floats per stage
#define NCHUNK (D / BK)              // 24
#define GEMM_SMEM (2 * SSTRIDE * 4)  // 73728 bytes

__global__ void __launch_bounds__(256, 2)
gemm_mma(const float* __restrict__ Aglob,
         const float* __restrict__ b0v, float* __restrict__ o0,
         const float* __restrict__ b1v, float* __restrict__ o1,
         const float* __restrict__ b2v, float* __restrict__ o2,
         int wsel, int head_layout) {
    extern __shared__ float smf[];
    uint32_t smb = smem_u32(smf);
    int tid = threadIdx.x;
    int z = blockIdx.z;
    const float* Wm = g_wt + (size_t)(wsel + z) * D * D;
    const float* bias = (z == 0) ? b0v : (z == 1) ? b1v : b2v;
    float* outp = (z == 0) ? o0 : (z == 1) ? o1 : o2;

    int r0 = blockIdx.y * BM;
    int c0 = blockIdx.x * BN;

    // staging assignment
    int srow = tid >> 1;            // 0..127
    int kq = (tid & 1) << 4;        // 0 or 16
    const float* aptr = Aglob + (size_t)(r0 + srow) * D + kq;
    const float* bptr = Wm + (size_t)(c0 + srow) * D + kq;
    uint32_t sa_off = (uint32_t)(srow * PADK + kq) * 4;

    int lane = tid & 31, wid = tid >> 5;
    int wm = wid >> 2, wn = wid & 3;       // warp grid 2 x 4
    int g = lane >> 2, t = lane & 3;

    float acc[4][4][4];
#pragma unroll
    for (int i = 0; i < 4; i++)
#pragma unroll
        for (int j = 0; j < 4; j++)
#pragma unroll
            for (int r = 0; r < 4; r++) acc[i][j][r] = 0.f;

    // prologue: stage chunk 0 into stage 0
    {
        uint32_t ab = smb + sa_off;
        uint32_t bb = ab + MATF * 4;
#pragma unroll
        for (int i = 0; i < 8; i++) {
            CP_ASYNC8(ab + i * 8, aptr + 2 * i);
            CP_ASYNC8(bb + i * 8, bptr + 2 * i);
        }
        CP_COMMIT();
    }

    for (int c = 0; c < NCHUNK; ++c) {
        if (c + 1 < NCHUNK) {
            uint32_t ab = smb + ((c + 1) & 1) * (SSTRIDE * 4) + sa_off;
            uint32_t bb = ab + MATF * 4;
            const float* ap = aptr + (c + 1) * BK;
            const float* bp = bptr + (c + 1) * BK;
#pragma unroll
            for (int i = 0; i < 8; i++) {
                CP_ASYNC8(ab + i * 8, ap + 2 * i);
                CP_ASYNC8(bb + i * 8, bp + 2 * i);
            }
            CP_COMMIT();
            asm volatile("cp.async.wait_group 1;" ::: "memory");
        } else {
            asm volatile("cp.async.wait_group 0;" ::: "memory");
        }
        __syncthreads();

        const float* As = smf + (c & 1) * SSTRIDE;
        const float* Bs = As + MATF;
#pragma unroll
        for (int ks = 0; ks < 4; ++ks) {
            int k = ks * 8;
            uint32_t af[4][4], bf[4][2];
#pragma unroll
            for (int mt = 0; mt < 4; mt++) {
                int m = wm * 64 + mt * 16 + g;
                af[mt][0] = __float_as_uint(As[m * PADK + k + t]);
                af[mt][1] = __float_as_uint(As[(m + 8) * PADK + k + t]);
                af[mt][2] = __float_as_uint(As[m * PADK + k + t + 4]);
                af[mt][3] = __float_as_uint(As[(m + 8) * PADK + k + t + 4]);
            }
#pragma unroll
            for (int nt = 0; nt < 4; nt++) {
                int n = wn * 32 + nt * 8 + g;
                bf[nt][0] = __float_as_uint(Bs[n * PADK + k + t]);
                bf[nt][1] = __float_as_uint(Bs[n * PADK + k + t + 4]);
            }
#pragma unroll
            for (int mt = 0; mt < 4; mt++)
#pragma unroll
                for (int nt = 0; nt < 4; nt++)
                    mma8(acc[mt][nt], af[mt], bf[nt]);
        }
        __syncthreads();
    }

    // epilogue: bias + store (optionally head layout)
#pragma unroll
    for (int mt = 0; mt < 4; mt++) {
#pragma unroll
        for (int nt = 0; nt < 4; nt++) {
            int cg = c0 + wn * 32 + nt * 8 + 2 * t;
            float b0 = bias[cg], b1 = bias[cg + 1];
#pragma unroll
            for (int half = 0; half < 2; half++) {
                int rg = r0 + wm * 64 + mt * 16 + g + half * 8;
                float2 val = make_float2(acc[mt][nt][half * 2 + 0] + b0,
                                         acc[mt][nt][half * 2 + 1] + b1);
                float* dst;
                if (head_layout) {
                    int bb = rg >> 9, n = rg & 511;
                    int hh = cg >> 6, dk = cg & 63;
                    dst = outp + (((size_t)(bb * H + hh) * N + n) * DK) + dk;
                } else {
                    dst = outp + (size_t)rg * D + cg;
                }
                *(float2*)dst = val;
            }
        }
    }
}

// ---------------- attention (unchanged except tf32-rounded g_ao store) ----------------
#define QT 32
#define KT 64
#define SMEM_ATTN ((64 * 32 + 64 * 64 + 32 * 512 + 32) * 4)

__global__ void __launch_bounds__(256) attn_kernel(const float* __restrict__ dist_emb,
                                                   float* __restrict__ att_out) {
    extern __shared__ float sm[];
    float* Qs = sm;
    float* KV = sm + 64 * 32;
    float* Sc = KV + 64 * 64;
    float* dh = Sc + 32 * 512;

    int tid = threadIdx.x;
    int bh = blockIdx.y;
    int b = bh / H;
    int h = bh - b * H;
    int q0 = blockIdx.x * QT;

    if (tid < ND) dh[tid] = dist_emb[tid * H + h];

    {
        int qi = tid >> 3;
        int d0 = (tid & 7) << 3;
        const float* qp = g_q + ((size_t)bh * N + q0 + qi) * DK + d0;
        float4 v0 = *(const float4*)qp;
        float4 v1 = *(const float4*)(qp + 4);
        Qs[(d0 + 0) * 32 + qi] = v0.x; Qs[(d0 + 1) * 32 + qi] = v0.y;
        Qs[(d0 + 2) * 32 + qi] = v0.z; Qs[(d0 + 3) * 32 + qi] = v0.w;
        Qs[(d0 + 4) * 32 + qi] = v1.x; Qs[(d0 + 5) * 32 + qi] = v1.y;
        Qs[(d0 + 6) * 32 + qi] = v1.z; Qs[(d0 + 7) * 32 + qi] = v1.w;
    }
    __syncthreads();

    int tx = tid & 15, ty = tid >> 4;
    const float scale = 0.125f;

    for (int kt = 0; kt < N; kt += KT) {
        int ki = tid >> 2;
        int d0 = (tid & 3) << 4;
        const float* kp = g_k + ((size_t)bh * N + kt + ki) * DK + d0;
#pragma unroll
        for (int t2 = 0; t2 < 4; t2++) {
            float4 v = *(const float4*)(kp + t2 * 4);
            KV[(d0 + t2 * 4 + 0) * 64 + ki] = v.x;
            KV[(d0 + t2 * 4 + 1) * 64 + ki] = v.y;
            KV[(d0 + t2 * 4 + 2) * 64 + ki] = v.z;
            KV[(d0 + t2 * 4 + 3) * 64 + ki] = v.w;
        }
        __syncthreads();
        float acc[2][4] = {};
        int qi2 = ty << 1, ki4 = tx << 2;
#pragma unroll 8
        for (int d = 0; d < DK; d++) {
            float a0 = Qs[d * 32 + qi2];
            float a1 = Qs[d * 32 + qi2 + 1];
            float4 bv = *(const float4*)&KV[d * 64 + ki4];
            acc[0][0] += a0 * bv.x; acc[0][1] += a0 * bv.y;
            acc[0][2] += a0 * bv.z; acc[0][3] += a0 * bv.w;
            acc[1][0] += a1 * bv.x; acc[1][1] += a1 * bv.y;
            acc[1][2] += a1 * bv.z; acc[1][3] += a1 * bv.w;
        }
#pragma unroll
        for (int i = 0; i < 2; i++) {
            *(float4*)&Sc[(qi2 + i) * 512 + kt + ki4] =
                make_float4(acc[i][0] * scale, acc[i][1] * scale,
                            acc[i][2] * scale, acc[i][3] * scale);
        }
        __syncthreads();
    }

    {
        int w = tid >> 5, lane = tid & 31;
#pragma unroll
        for (int rr = 0; rr < 4; rr++) {
            int qi = w + (rr << 3);
            int qg = q0 + qi;
            const unsigned char* brow = g_bins + ((size_t)b * N + qg) * N;
            float* srow = Sc + qi * 512;
            float m = -1e30f;
            for (int kk = lane; kk < N; kk += 32) {
                float s = srow[kk] + dh[brow[kk]];
                srow[kk] = s;
                m = fmaxf(m, s);
            }
#pragma unroll
            for (int o = 16; o; o >>= 1) m = fmaxf(m, __shfl_xor_sync(~0u, m, o));
            float ssum = 0.f;
            for (int kk = lane; kk < N; kk += 32) {
                float e = __expf(srow[kk] - m);
                srow[kk] = e;
                ssum += e;
            }
#pragma unroll
            for (int o = 16; o; o >>= 1) ssum += __shfl_xor_sync(~0u, ssum, o);
            float inv = 1.0f / ssum;
            float* arow = att_out + ((size_t)bh * N + qg) * N;
            for (int kk = lane; kk < N; kk += 32) {
                float p = srow[kk] * inv;
                srow[kk] = p;
                arow[kk] = p;
            }
        }
    }
    __syncthreads();

    float oacc[2][4] = {};
    int qi2 = ty << 1, dk4 = tx << 2;
    for (int kt = 0; kt < N; kt += KT) {
        int ki = tid >> 2;
        int d0 = (tid & 3) << 4;
        const float* vp = g_v + ((size_t)bh * N + kt + ki) * DK + d0;
#pragma unroll
        for (int t2 = 0; t2 < 4; t2++) {
            *(float4*)&KV[ki * 64 + d0 + t2 * 4] = *(const float4*)(vp + t2 * 4);
        }
        __syncthreads();
#pragma unroll 8
        for (int ki2 = 0; ki2 < KT; ki2++) {
            float a0 = Sc[qi2 * 512 + kt + ki2];
            float a1 = Sc[(qi2 + 1) * 512 + kt + ki2];
            float4 bv = *(const float4*)&KV[ki2 * 64 + dk4];
            oacc[0][0] += a0 * bv.x; oacc[0][1] += a0 * bv.y;
            oacc[0][2] += a0 * bv.z; oacc[0][3] += a0 * bv.w;
            oacc[1][0] += a1 * bv.x; oacc[1][1] += a1 * bv.y;
            oacc[1][2] += a1 * bv.z; oacc[1][3] += a1 * bv.w;
        }
        __syncthreads();
    }
#pragma unroll
    for (int i = 0; i < 2; i++) {
        int qg = q0 + qi2 + i;
        *(float4*)&g_ao[((size_t)b * N + qg) * D + h * DK + dk4] =
            make_float4(to_tf32(oacc[i][0]), to_tf32(oacc[i][1]),
                        to_tf32(oacc[i][2]), to_tf32(oacc[i][3]));
    }
}

// ---------------- launch ----------------
extern "C" void kernel_launch(void* const* d_in, const int* in_sizes, int n_in,
                              void* d_out, int out_size) {
    const float* features = (const float*)d_in[0];
    const float* boxes    = (const float*)d_in[1];
    const int*   iszs     = (const int*)  d_in[2];
    const float* Wq = (const float*)d_in[3];
    const float* bq = (const float*)d_in[4];
    const float* Wk = (const float*)d_in[5];
    const float* bk = (const float*)d_in[6];
    const float* Wv = (const float*)d_in[7];
    const float* bv = (const float*)d_in[8];
    const float* Wo = (const float*)d_in[9];
    const float* bo = (const float*)d_in[10];
    const float* gamma = (const float*)d_in[11];
    const float* beta  = (const float*)d_in[12];
    const float* dist_emb = (const float*)d_in[13];

    float* out = (float*)d_out;
    float* att = ((size_t)out_size >= OUT_ELEMS + ATT_ELEMS) ? out + OUT_ELEMS : out;

    cudaFuncSetAttribute(attn_kernel, cudaFuncAttributeMaxDynamicSharedMemorySize, SMEM_ATTN);
    cudaFuncSetAttribute(gemm_mma, cudaFuncAttributeMaxDynamicSharedMemorySize, GEMM_SMEM);

    float *gx, *gq, *gk, *gv, *gao;
    cudaGetSymbolAddress((void**)&gx, g_x);
    cudaGetSymbolAddress((void**)&gq, g_q);
    cudaGetSymbolAddress((void**)&gk, g_k);
    cudaGetSymbolAddress((void**)&gv, g_v);
    cudaGetSymbolAddress((void**)&gao, g_ao);

    ln_kernel<<<ROWS, 256>>>(features, gamma, beta);
    cvt_w<<<dim3((D * D) / 256, 4), 256>>>(Wq, Wk, Wv, Wo);
    patch_kernel<<<(ROWS + 255) / 256, 256>>>(boxes, iszs);
    bins_kernel<<<(B * N * N) / 256, 256>>>();

    // QKV projections (head layout), weights g_wt[0..2]
    dim3 gq3(D / BN, ROWS / BM, 3);
    gemm_mma<<<gq3, 256, GEMM_SMEM>>>(gx, bq, gq, bk, gk, bv, gv, 0, 1);

    dim3 ga(N / QT, B * H);
    attn_kernel<<<ga, 256, SMEM_ATTN>>>(dist_emb, att);

    // output projection (row-major), weight g_wt[3]
    dim3 go3(D / BN, ROWS / BM, 1);
    gemm_mma<<<go3, 256, GEMM_SMEM>>>(gao, bo, out, bo, out, bo, out, 3, 0);
}

// round 4
// speedup vs baseline: 2.4249x; 1.4388x over previous
#include <cuda_runtime.h>
#include <math.h>
#include <stdint.h>

#define B 16
#define N 512
#define D 768
#define H 12
#define DK 64
#define ND 32
#define ROWS (B * N)
#define OUT_ELEMS ((size_t)B * N * D)
#define ATT_ELEMS ((size_t)B * H * N * N)

// ---------------- scratch ----------------
__device__ float g_x[ROWS * D];
__device__ float g_q[ROWS * D];
__device__ float g_k[ROWS * D];
__device__ float g_v[ROWS * D];
__device__ float g_ao[ROWS * D];
__device__ float g_wt[4 * D * D];
__device__ int g_px[ROWS];
__device__ int g_py[ROWS];
__device__ unsigned char g_bins[B * N * N];

__device__ __forceinline__ float to_tf32(float x) {
    uint32_t u;
    asm("cvt.rna.tf32.f32 %0, %1;" : "=r"(u) : "f"(x));
    return __uint_as_float(u);
}
__device__ __forceinline__ uint32_t smem_u32(const void* p) {
    uint32_t a;
    asm("{ .reg .u64 t; cvta.to.shared.u64 t, %1; cvt.u32.u64 %0, t; }" : "=r"(a) : "l"(p));
    return a;
}
#define CP_ASYNC8(dst, src)  asm volatile("cp.async.ca.shared.global [%0], [%1], 8;" :: "r"(dst), "l"(src) : "memory")
#define CP_ASYNC16(dst, src) asm volatile("cp.async.cg.shared.global [%0], [%1], 16;" :: "r"(dst), "l"(src) : "memory")
#define CP_COMMIT()          asm volatile("cp.async.commit_group;" ::: "memory")
#define CP_WAIT(nn)          asm volatile("cp.async.wait_group %0;" :: "n"(nn) : "memory")

__device__ __forceinline__ void mma8(float* d, const uint32_t* a, const uint32_t* b) {
    asm volatile("mma.sync.aligned.m16n8k8.row.col.f32.tf32.tf32.f32 "
                 "{%0,%1,%2,%3}, {%4,%5,%6,%7}, {%8,%9}, {%0,%1,%2,%3};"
                 : "+f"(d[0]), "+f"(d[1]), "+f"(d[2]), "+f"(d[3])
                 : "r"(a[0]), "r"(a[1]), "r"(a[2]), "r"(a[3]), "r"(b[0]), "r"(b[1]));
}

// ---------------- LayerNorm (writes tf32-rounded) ----------------
__global__ void __launch_bounds__(256) ln_kernel(const float* __restrict__ f,
                                                 const float* __restrict__ gamma,
                                                 const float* __restrict__ beta) {
    int row = blockIdx.x;
    int t = threadIdx.x;
    const float* x = f + (size_t)row * D;
    float v[3];
    float s = 0.f, s2 = 0.f;
#pragma unroll
    for (int i = 0; i < 3; i++) {
        v[i] = x[t + i * 256];
        s += v[i];
        s2 += v[i] * v[i];
    }
    __shared__ float redA[8], redB[8];
#pragma unroll
    for (int o = 16; o; o >>= 1) {
        s += __shfl_xor_sync(~0u, s, o);
        s2 += __shfl_xor_sync(~0u, s2, o);
    }
    if ((t & 31) == 0) { redA[t >> 5] = s; redB[t >> 5] = s2; }
    __syncthreads();
    if (t < 32) {
        float a = (t < 8) ? redA[t] : 0.f;
        float c = (t < 8) ? redB[t] : 0.f;
#pragma unroll
        for (int o = 4; o; o >>= 1) {
            a += __shfl_xor_sync(~0u, a, o);
            c += __shfl_xor_sync(~0u, c, o);
        }
        if (t == 0) { redA[0] = a; redB[0] = c; }
    }
    __syncthreads();
    float mu = redA[0] * (1.0f / D);
    float var = redB[0] * (1.0f / D) - mu * mu;
    float rstd = rsqrtf(var + 1e-5f);
    float* xo = g_x + (size_t)row * D;
#pragma unroll
    for (int i = 0; i < 3; i++) {
        int c = t + i * 256;
        xo[c] = to_tf32((v[i] - mu) * rstd * gamma[c] + beta[c]);
    }
}

__global__ void __launch_bounds__(256) cvt_w(const float* __restrict__ Wq,
                                             const float* __restrict__ Wk,
                                             const float* __restrict__ Wv,
                                             const float* __restrict__ Wo) {
    int i = blockIdx.x * 256 + threadIdx.x;
    int z = blockIdx.y;
    const float* src = (z == 0) ? Wq : (z == 1) ? Wk : (z == 2) ? Wv : Wo;
    g_wt[(size_t)z * D * D + i] = to_tf32(src[i]);
}

__global__ void patch_kernel(const float* __restrict__ boxes,
                             const int* __restrict__ iszs) {
    int idx = blockIdx.x * 256 + threadIdx.x;
    if (idx >= ROWS) return;
    int b = idx >> 9;
    float w = (float)iszs[b * 4 + 0];
    float h = (float)iszs[b * 4 + 1];
    const float* bx = boxes + (size_t)idx * 4;
    float p0 = bx[0] * w, p1 = bx[1] * h, p2 = bx[2] * w, p3 = bx[3] * h;
    float spw = floorf(w / 11.0f);
    float sph = floorf(h / 11.0f);
    float cx = floorf((p0 + p2) * 0.5f);
    float cy = floorf((p1 + p3) * 0.5f);
    int px = 0, py = 0;
    bool fx = false, fy = false;
#pragma unroll
    for (int j = 0; j < 11; j++) {
        float jl = (float)j, jh = (float)(j + 1);
        float lo = jl * spw, hi = jh * spw;
        if (!fx && lo <= cx && cx <= hi) { px = j; fx = true; }
        float lo2 = jl * sph, hi2 = jh * sph;
        if (!fy && lo2 <= cy && cy <= hi2) { py = j; fy = true; }
    }
    g_px[idx] = px;
    g_py[idx] = py;
}

__global__ void bins_kernel() {
    int idx = blockIdx.x * 256 + threadIdx.x;
    int j = idx & (N - 1);
    int i = (idx >> 9) & (N - 1);
    int b = idx >> 18;
    float dx = (float)(g_px[b * N + j] - g_px[b * N + i]);
    float dy = (float)(g_py[b * N + j] - g_py[b * N + i]);
    g_bins[idx] = (unsigned char)(int)(sqrtf(dx * dx + dy * dy) * 2.0f);
}

// ================ mma.sync tf32 GEMM: C[8192,768] = A @ W^T + bias ================
#define BM 128
#define BN 128
#define BK 32
#define PADK 36
#define MATF (BM * PADK)
#define SSTRIDE (2 * MATF)
#define NCHUNK (D / BK)
#define GEMM_SMEM (2 * SSTRIDE * 4)

__global__ void __launch_bounds__(256, 2)
gemm_mma(const float* __restrict__ Aglob,
         const float* __restrict__ b0v, float* __restrict__ o0,
         const float* __restrict__ b1v, float* __restrict__ o1,
         const float* __restrict__ b2v, float* __restrict__ o2,
         int wsel, int head_layout) {
    extern __shared__ float smf[];
    uint32_t smb = smem_u32(smf);
    int tid = threadIdx.x;
    int z = blockIdx.z;
    const float* Wm = g_wt + (size_t)(wsel + z) * D * D;
    const float* bias = (z == 0) ? b0v : (z == 1) ? b1v : b2v;
    float* outp = (z == 0) ? o0 : (z == 1) ? o1 : o2;

    int r0 = blockIdx.y * BM;
    int c0 = blockIdx.x * BN;

    int srow = tid >> 1;
    int kq = (tid & 1) << 4;
    const float* aptr = Aglob + (size_t)(r0 + srow) * D + kq;
    const float* bptr = Wm + (size_t)(c0 + srow) * D + kq;
    uint32_t sa_off = (uint32_t)(srow * PADK + kq) * 4;

    int lane = tid & 31, wid = tid >> 5;
    int wm = wid >> 2, wn = wid & 3;
    int g = lane >> 2, t = lane & 3;

    float acc[4][4][4];
#pragma unroll
    for (int i = 0; i < 4; i++)
#pragma unroll
        for (int j = 0; j < 4; j++)
#pragma unroll
            for (int r = 0; r < 4; r++) acc[i][j][r] = 0.f;

    {
        uint32_t ab = smb + sa_off;
        uint32_t bb = ab + MATF * 4;
#pragma unroll
        for (int i = 0; i < 8; i++) {
            CP_ASYNC8(ab + i * 8, aptr + 2 * i);
            CP_ASYNC8(bb + i * 8, bptr + 2 * i);
        }
        CP_COMMIT();
    }

    for (int c = 0; c < NCHUNK; ++c) {
        if (c + 1 < NCHUNK) {
            uint32_t ab = smb + ((c + 1) & 1) * (SSTRIDE * 4) + sa_off;
            uint32_t bb = ab + MATF * 4;
            const float* ap = aptr + (c + 1) * BK;
            const float* bp = bptr + (c + 1) * BK;
#pragma unroll
            for (int i = 0; i < 8; i++) {
                CP_ASYNC8(ab + i * 8, ap + 2 * i);
                CP_ASYNC8(bb + i * 8, bp + 2 * i);
            }
            CP_COMMIT();
            CP_WAIT(1);
        } else {
            CP_WAIT(0);
        }
        __syncthreads();

        const float* As = smf + (c & 1) * SSTRIDE;
        const float* Bs = As + MATF;
#pragma unroll
        for (int ks = 0; ks < 4; ++ks) {
            int k = ks * 8;
            uint32_t af[4][4], bf[4][2];
#pragma unroll
            for (int mt = 0; mt < 4; mt++) {
                int m = wm * 64 + mt * 16 + g;
                af[mt][0] = __float_as_uint(As[m * PADK + k + t]);
                af[mt][1] = __float_as_uint(As[(m + 8) * PADK + k + t]);
                af[mt][2] = __float_as_uint(As[m * PADK + k + t + 4]);
                af[mt][3] = __float_as_uint(As[(m + 8) * PADK + k + t + 4]);
            }
#pragma unroll
            for (int nt = 0; nt < 4; nt++) {
                int n = wn * 32 + nt * 8 + g;
                bf[nt][0] = __float_as_uint(Bs[n * PADK + k + t]);
                bf[nt][1] = __float_as_uint(Bs[n * PADK + k + t + 4]);
            }
#pragma unroll
            for (int mt = 0; mt < 4; mt++)
#pragma unroll
                for (int nt = 0; nt < 4; nt++)
                    mma8(acc[mt][nt], af[mt], bf[nt]);
        }
        __syncthreads();
    }

#pragma unroll
    for (int mt = 0; mt < 4; mt++) {
#pragma unroll
        for (int nt = 0; nt < 4; nt++) {
            int cg = c0 + wn * 32 + nt * 8 + 2 * t;
            float b0 = bias[cg], b1 = bias[cg + 1];
#pragma unroll
            for (int half = 0; half < 2; half++) {
                int rg = r0 + wm * 64 + mt * 16 + g + half * 8;
                float v0 = acc[mt][nt][half * 2 + 0] + b0;
                float v1 = acc[mt][nt][half * 2 + 1] + b1;
                float* dst;
                if (head_layout) {
                    int bb = rg >> 9, n = rg & 511;
                    int hh = cg >> 6, dk = cg & 63;
                    dst = outp + (((size_t)(bb * H + hh) * N + n) * DK) + dk;
                    *(float2*)dst = make_float2(to_tf32(v0), to_tf32(v1));
                } else {
                    dst = outp + (size_t)rg * D + cg;
                    *(float2*)dst = make_float2(v0, v1);
                }
            }
        }
    }
}

// ================ attention with mma.sync tf32 ================
// CTA: one (b,h) x 64 q rows. 8 warps (2 x 4). smem: Qs[64][68], 2x K/V
// chunk buffers [64][68], Sc[64][516], dh[32]. Conflict-free fragment gathers.
#define PADA 68
#define PADS 516
#define QS_OFF 0
#define KB0_OFF (64 * PADA)                 // 4352
#define KB1_OFF (2 * 64 * PADA)             // 8704
#define SC_OFF  (3 * 64 * PADA)             // 13056
#define DH_OFF  (SC_OFF + 64 * PADS)        // 46080
#define ATT_SMEM ((DH_OFF + 32) * 4)        // 184448 bytes

__device__ __forceinline__ void load_chunk64(uint32_t dst_base, const float* src) {
    int tid = threadIdx.x;
#pragma unroll
    for (int it = 0; it < 4; ++it) {
        int idx = tid + it * 256;
        int row = idx >> 4, seg = idx & 15;
        CP_ASYNC16(dst_base + (uint32_t)(row * PADA + seg * 4) * 4, src + idx * 4);
    }
}

__global__ void __launch_bounds__(256, 1) attn_mma(const float* __restrict__ dist_emb,
                                                   float* __restrict__ att_out) {
    extern __shared__ float sm[];
    uint32_t smb = smem_u32(sm);
    float* Qs = sm + QS_OFF;
    float* Sc = sm + SC_OFF;
    float* dh = sm + DH_OFF;

    int tid = threadIdx.x;
    int bh = blockIdx.y;
    int b = bh / H;
    int h = bh - b * H;
    int q0 = blockIdx.x * 64;

    if (tid < ND) dh[tid] = dist_emb[tid * H + h];

    const float* Qg = g_q + ((size_t)bh * N + q0) * DK;
    const float* Kg = g_k + (size_t)bh * N * DK;
    const float* Vg = g_v + (size_t)bh * N * DK;

    int lane = tid & 31, wid = tid >> 5;
    int wm = wid >> 2, wn = wid & 3;      // 2 x 4
    int g = lane >> 2, t = lane & 3;
    const float scale = 0.125f;

    // prologue: Q + K chunk 0
    load_chunk64(smb + QS_OFF * 4, Qg);
    load_chunk64(smb + KB0_OFF * 4, Kg);
    CP_COMMIT();

    // ---------- phase 1: S = Q K^T * scale ----------
    for (int kt = 0; kt < 8; ++kt) {
        if (kt < 7) {
            load_chunk64(smb + (((kt + 1) & 1) ? KB1_OFF : KB0_OFF) * 4, Kg + (kt + 1) * 4096);
            CP_COMMIT();
            CP_WAIT(1);
        } else {
            CP_WAIT(0);
        }
        __syncthreads();
        const float* Ks = sm + ((kt & 1) ? KB1_OFF : KB0_OFF);
        float acc[2][2][4];
#pragma unroll
        for (int i = 0; i < 2; i++)
#pragma unroll
            for (int j = 0; j < 2; j++)
#pragma unroll
                for (int r = 0; r < 4; r++) acc[i][j][r] = 0.f;
#pragma unroll
        for (int ks = 0; ks < 8; ++ks) {
            int k = ks * 8;
            uint32_t af[2][4], bf[2][2];
#pragma unroll
            for (int mt = 0; mt < 2; mt++) {
                int m = wm * 32 + mt * 16 + g;
                af[mt][0] = __float_as_uint(Qs[m * PADA + k + t]);
                af[mt][1] = __float_as_uint(Qs[(m + 8) * PADA + k + t]);
                af[mt][2] = __float_as_uint(Qs[m * PADA + k + t + 4]);
                af[mt][3] = __float_as_uint(Qs[(m + 8) * PADA + k + t + 4]);
            }
#pragma unroll
            for (int nt = 0; nt < 2; nt++) {
                int n = wn * 16 + nt * 8 + g;
                bf[nt][0] = __float_as_uint(Ks[n * PADA + k + t]);
                bf[nt][1] = __float_as_uint(Ks[n * PADA + k + t + 4]);
            }
#pragma unroll
            for (int mt = 0; mt < 2; mt++)
#pragma unroll
                for (int nt = 0; nt < 2; nt++)
                    mma8(acc[mt][nt], af[mt], bf[nt]);
        }
#pragma unroll
        for (int mt = 0; mt < 2; mt++) {
#pragma unroll
            for (int nt = 0; nt < 2; nt++) {
                int row = wm * 32 + mt * 16 + g;
                int col = kt * 64 + wn * 16 + nt * 8 + 2 * t;
                *(float2*)&Sc[row * PADS + col] =
                    make_float2(acc[mt][nt][0] * scale, acc[mt][nt][1] * scale);
                *(float2*)&Sc[(row + 8) * PADS + col] =
                    make_float2(acc[mt][nt][2] * scale, acc[mt][nt][3] * scale);
            }
        }
        __syncthreads();
    }

    // ---------- phase 2: softmax + bias, write att, tf32 P into Sc ----------
#pragma unroll
    for (int rr = 0; rr < 8; rr++) {
        int qi = wid * 8 + rr;
        int qg = q0 + qi;
        const unsigned char* brow = g_bins + ((size_t)b * N + qg) * N;
        float* srow = Sc + qi * PADS;
        float m = -1e30f;
        for (int kk = lane; kk < N; kk += 32) {
            float s = srow[kk] + dh[brow[kk]];
            srow[kk] = s;
            m = fmaxf(m, s);
        }
#pragma unroll
        for (int o = 16; o; o >>= 1) m = fmaxf(m, __shfl_xor_sync(~0u, m, o));
        float ssum = 0.f;
        for (int kk = lane; kk < N; kk += 32) {
            float e = __expf(srow[kk] - m);
            srow[kk] = e;
            ssum += e;
        }
#pragma unroll
        for (int o = 16; o; o >>= 1) ssum += __shfl_xor_sync(~0u, ssum, o);
        float inv = 1.0f / ssum;
        float* arow = att_out + ((size_t)bh * N + qg) * N;
        for (int kk = lane; kk < N; kk += 32) {
            float p = srow[kk] * inv;
            arow[kk] = p;
            srow[kk] = to_tf32(p);
        }
    }

    // ---------- phase 3: O = P V ----------
    load_chunk64(smb + KB0_OFF * 4, Vg);
    CP_COMMIT();
    float oacc[2][2][4];
#pragma unroll
    for (int i = 0; i < 2; i++)
#pragma unroll
        for (int j = 0; j < 2; j++)
#pragma unroll
            for (int r = 0; r < 4; r++) oacc[i][j][r] = 0.f;

    for (int kt = 0; kt < 8; ++kt) {
        if (kt < 7) {
            load_chunk64(smb + (((kt + 1) & 1) ? KB1_OFF : KB0_OFF) * 4, Vg + (kt + 1) * 4096);
            CP_COMMIT();
            CP_WAIT(1);
        } else {
            CP_WAIT(0);
        }
        __syncthreads();
        const float* Vs = sm + ((kt & 1) ? KB1_OFF : KB0_OFF);
#pragma unroll
        for (int ks = 0; ks < 8; ++ks) {
            int k = ks * 8;
            uint32_t af[2][4], bf[2][2];
#pragma unroll
            for (int mt = 0; mt < 2; mt++) {
                int m = wm * 32 + mt * 16 + g;
                int sb = m * PADS + kt * 64 + k;
                af[mt][0] = __float_as_uint(Sc[sb + t]);
                af[mt][1] = __float_as_uint(Sc[sb + 8 * PADS + t]);
                af[mt][2] = __float_as_uint(Sc[sb + t + 4]);
                af[mt][3] = __float_as_uint(Sc[sb + 8 * PADS + t + 4]);
            }
#pragma unroll
            for (int nt = 0; nt < 2; nt++) {
                int n = wn * 16 + nt * 8 + g;
                bf[nt][0] = __float_as_uint(Vs[(k + t) * PADA + n]);
                bf[nt][1] = __float_as_uint(Vs[(k + t + 4) * PADA + n]);
            }
#pragma unroll
            for (int mt = 0; mt < 2; mt++)
#pragma unroll
                for (int nt = 0; nt < 2; nt++)
                    mma8(oacc[mt][nt], af[mt], bf[nt]);
        }
        __syncthreads();
    }

    // epilogue: write ao (tf32-rounded; feeds out-proj mma)
#pragma unroll
    for (int mt = 0; mt < 2; mt++) {
#pragma unroll
        for (int nt = 0; nt < 2; nt++) {
            int dk = wn * 16 + nt * 8 + 2 * t;
#pragma unroll
            for (int half = 0; half < 2; half++) {
                int qg = q0 + wm * 32 + mt * 16 + g + half * 8;
                float* dst = g_ao + ((size_t)(b * N + qg)) * D + h * DK + dk;
                *(float2*)dst = make_float2(to_tf32(oacc[mt][nt][half * 2 + 0]),
                                            to_tf32(oacc[mt][nt][half * 2 + 1]));
            }
        }
    }
}

// ---------------- launch ----------------
extern "C" void kernel_launch(void* const* d_in, const int* in_sizes, int n_in,
                              void* d_out, int out_size) {
    const float* features = (const float*)d_in[0];
    const float* boxes    = (const float*)d_in[1];
    const int*   iszs     = (const int*)  d_in[2];
    const float* Wq = (const float*)d_in[3];
    const float* bq = (const float*)d_in[4];
    const float* Wk = (const float*)d_in[5];
    const float* bk = (const float*)d_in[6];
    const float* Wv = (const float*)d_in[7];
    const float* bv = (const float*)d_in[8];
    const float* Wo = (const float*)d_in[9];
    const float* bo = (const float*)d_in[10];
    const float* gamma = (const float*)d_in[11];
    const float* beta  = (const float*)d_in[12];
    const float* dist_emb = (const float*)d_in[13];

    float* out = (float*)d_out;
    float* att = ((size_t)out_size >= OUT_ELEMS + ATT_ELEMS) ? out + OUT_ELEMS : out;

    cudaFuncSetAttribute(attn_mma, cudaFuncAttributeMaxDynamicSharedMemorySize, ATT_SMEM);
    cudaFuncSetAttribute(gemm_mma, cudaFuncAttributeMaxDynamicSharedMemorySize, GEMM_SMEM);

    float *gx, *gq, *gk, *gv, *gao;
    cudaGetSymbolAddress((void**)&gx, g_x);
    cudaGetSymbolAddress((void**)&gq, g_q);
    cudaGetSymbolAddress((void**)&gk, g_k);
    cudaGetSymbolAddress((void**)&gv, g_v);
    cudaGetSymbolAddress((void**)&gao, g_ao);

    ln_kernel<<<ROWS, 256>>>(features, gamma, beta);
    cvt_w<<<dim3((D * D) / 256, 4), 256>>>(Wq, Wk, Wv, Wo);
    patch_kernel<<<(ROWS + 255) / 256, 256>>>(boxes, iszs);
    bins_kernel<<<(B * N * N) / 256, 256>>>();

    dim3 gq3(D / BN, ROWS / BM, 3);
    gemm_mma<<<gq3, 256, GEMM_SMEM>>>(gx, bq, gq, bk, gk, bv, gv, 0, 1);

    dim3 ga(N / 64, B * H);
    attn_mma<<<ga, 256, ATT_SMEM>>>(dist_emb, att);

    dim3 go3(D / BN, ROWS / BM, 1);
    gemm_mma<<<go3, 256, GEMM_SMEM>>>(gao, bo, out, bo, out, bo, out, 3, 0);
}

// round 8
// speedup vs baseline: 3.6926x; 1.5228x over previous
#include <cuda_runtime.h>
#include <math.h>
#include <stdint.h>

#define B 16
#define N 512
#define D 768
#define H 12
#define DK 64
#define ND 32
#define ROWS (B * N)
#define OUT_ELEMS ((size_t)B * N * D)
#define ATT_ELEMS ((size_t)B * H * N * N)

// ---------------- scratch ----------------
__device__ float g_x[ROWS * D];
__device__ float g_q[ROWS * D];
__device__ float g_k[ROWS * D];
__device__ float g_v[ROWS * D];
__device__ float g_ao[ROWS * D];
__device__ float g_wt[4 * D * D];
__device__ int g_px[ROWS];
__device__ int g_py[ROWS];

__device__ __forceinline__ float to_tf32(float x) {
    uint32_t u;
    asm("cvt.rna.tf32.f32 %0, %1;" : "=r"(u) : "f"(x));
    return __uint_as_float(u);
}
__device__ __forceinline__ uint32_t smem_u32(const void* p) {
    uint32_t a;
    asm("{ .reg .u64 t; cvta.to.shared.u64 t, %1; cvt.u32.u64 %0, t; }" : "=r"(a) : "l"(p));
    return a;
}
#define CP_ASYNC16(dst, src) asm volatile("cp.async.cg.shared.global [%0], [%1], 16;" :: "r"(dst), "l"(src) : "memory")
#define CP_COMMIT()          asm volatile("cp.async.commit_group;" ::: "memory")
#define CP_WAIT(nn)          asm volatile("cp.async.wait_group %0;" :: "n"(nn) : "memory")

__device__ __forceinline__ void mma8(float* d, const uint32_t* a, const uint32_t* b) {
    asm volatile("mma.sync.aligned.m16n8k8.row.col.f32.tf32.tf32.f32 "
                 "{%0,%1,%2,%3}, {%4,%5,%6,%7}, {%8,%9}, {%0,%1,%2,%3};"
                 : "+f"(d[0]), "+f"(d[1]), "+f"(d[2]), "+f"(d[3])
                 : "r"(a[0]), "r"(a[1]), "r"(a[2]), "r"(a[3]), "r"(b[0]), "r"(b[1]));
}

// ---------------- LayerNorm (writes tf32-rounded) ----------------
__global__ void __launch_bounds__(256) ln_kernel(const float* __restrict__ f,
                                                 const float* __restrict__ gamma,
                                                 const float* __restrict__ beta) {
    int row = blockIdx.x;
    int t = threadIdx.x;
    const float* x = f + (size_t)row * D;
    float v[3];
    float s = 0.f, s2 = 0.f;
#pragma unroll
    for (int i = 0; i < 3; i++) {
        v[i] = x[t + i * 256];
        s += v[i];
        s2 += v[i] * v[i];
    }
    __shared__ float redA[8], redB[8];
#pragma unroll
    for (int o = 16; o; o >>= 1) {
        s += __shfl_xor_sync(~0u, s, o);
        s2 += __shfl_xor_sync(~0u, s2, o);
    }
    if ((t & 31) == 0) { redA[t >> 5] = s; redB[t >> 5] = s2; }
    __syncthreads();
    if (t < 32) {
        float a = (t < 8) ? redA[t] : 0.f;
        float c = (t < 8) ? redB[t] : 0.f;
#pragma unroll
        for (int o = 4; o; o >>= 1) {
            a += __shfl_xor_sync(~0u, a, o);
            c += __shfl_xor_sync(~0u, c, o);
        }
        if (t == 0) { redA[0] = a; redB[0] = c; }
    }
    __syncthreads();
    float mu = redA[0] * (1.0f / D);
    float var = redB[0] * (1.0f / D) - mu * mu;
    float rstd = rsqrtf(var + 1e-5f);
    float* xo = g_x + (size_t)row * D;
#pragma unroll
    for (int i = 0; i < 3; i++) {
        int c = t + i * 256;
        xo[c] = to_tf32((v[i] - mu) * rstd * gamma[c] + beta[c]);
    }
}

__global__ void __launch_bounds__(256) cvt_w(const float* __restrict__ Wq,
                                             const float* __restrict__ Wk,
                                             const float* __restrict__ Wv,
                                             const float* __restrict__ Wo) {
    int i = blockIdx.x * 256 + threadIdx.x;
    int z = blockIdx.y;
    const float* src = (z == 0) ? Wq : (z == 1) ? Wk : (z == 2) ? Wv : Wo;
    g_wt[(size_t)z * D * D + i] = to_tf32(src[i]);
}

__global__ void patch_kernel(const float* __restrict__ boxes,
                             const int* __restrict__ iszs) {
    int idx = blockIdx.x * 256 + threadIdx.x;
    if (idx >= ROWS) return;
    int b = idx >> 9;
    float w = (float)iszs[b * 4 + 0];
    float h = (float)iszs[b * 4 + 1];
    const float* bx = boxes + (size_t)idx * 4;
    float p0 = bx[0] * w, p1 = bx[1] * h, p2 = bx[2] * w, p3 = bx[3] * h;
    float spw = floorf(w / 11.0f);
    float sph = floorf(h / 11.0f);
    float cx = floorf((p0 + p2) * 0.5f);
    float cy = floorf((p1 + p3) * 0.5f);
    int px = 0, py = 0;
    bool fx = false, fy = false;
#pragma unroll
    for (int j = 0; j < 11; j++) {
        float jl = (float)j, jh = (float)(j + 1);
        float lo = jl * spw, hi = jh * spw;
        if (!fx && lo <= cx && cx <= hi) { px = j; fx = true; }
        float lo2 = jl * sph, hi2 = jh * sph;
        if (!fy && lo2 <= cy && cy <= hi2) { py = j; fy = true; }
    }
    g_px[idx] = px;
    g_py[idx] = py;
}

// ================ mma.sync tf32 GEMM: C[8192,768] = A @ W^T + bias ================
// BM=128, BN=256, BK=32. 8 warps (2x4), warp tile 64x64 (4 m-tiles x 8 n-tiles).
#define BM 128
#define BN 256
#define BK 32
#define PADK 36
#define AF (BM * PADK)                 // 4608 floats
#define BF (BN * PADK)                 // 9216 floats
#define SSTRIDE (AF + BF)              // 13824 floats per stage
#define NCHUNK (D / BK)                // 24
#define GEMM_SMEM (2 * SSTRIDE * 4)    // 110592 bytes

__global__ void __launch_bounds__(256, 1)
gemm_mma(const float* __restrict__ Aglob,
         const float* __restrict__ b0v, float* __restrict__ o0,
         const float* __restrict__ b1v, float* __restrict__ o1,
         const float* __restrict__ b2v, float* __restrict__ o2,
         int wsel, int head_layout) {
    extern __shared__ float smf[];
    uint32_t smb = smem_u32(smf);
    int tid = threadIdx.x;
    int z = blockIdx.z;
    const float* Wm = g_wt + (size_t)(wsel + z) * D * D;
    const float* bias = (z == 0) ? b0v : (z == 1) ? b1v : b2v;
    float* outp = (z == 0) ? o0 : (z == 1) ? o1 : o2;

    int r0 = blockIdx.y * BM;
    int c0 = blockIdx.x * BN;

    int lane = tid & 31, wid = tid >> 5;
    int wm = wid >> 2, wn = wid & 3;
    int g = lane >> 2, t = lane & 3;

    float acc[4][8][4];
#pragma unroll
    for (int i = 0; i < 4; i++)
#pragma unroll
        for (int j = 0; j < 8; j++)
#pragma unroll
            for (int r = 0; r < 4; r++) acc[i][j][r] = 0.f;

#define STAGE_CHUNK(cc, sbase)                                                      \
    do {                                                                            \
        uint32_t ab = (sbase);                                                      \
        uint32_t bb = (sbase) + AF * 4;                                             \
        _Pragma("unroll")                                                           \
        for (int i = 0; i < 4; i++) {                                               \
            int f = tid + i * 256;                                                  \
            int row = f >> 3, seg = f & 7;                                          \
            CP_ASYNC16(ab + (uint32_t)(row * PADK + seg * 4) * 4,                   \
                       Aglob + (size_t)(r0 + row) * D + (cc) * BK + seg * 4);       \
        }                                                                           \
        _Pragma("unroll")                                                           \
        for (int i = 0; i < 8; i++) {                                               \
            int f = tid + i * 256;                                                  \
            int row = f >> 3, seg = f & 7;                                          \
            CP_ASYNC16(bb + (uint32_t)(row * PADK + seg * 4) * 4,                   \
                       Wm + (size_t)(c0 + row) * D + (cc) * BK + seg * 4);          \
        }                                                                           \
        CP_COMMIT();                                                                \
    } while (0)

    STAGE_CHUNK(0, smb);

    for (int c = 0; c < NCHUNK; ++c) {
        if (c + 1 < NCHUNK) {
            STAGE_CHUNK(c + 1, smb + ((c + 1) & 1) * (SSTRIDE * 4));
            CP_WAIT(1);
        } else {
            CP_WAIT(0);
        }
        __syncthreads();

        const float* As = smf + (c & 1) * SSTRIDE;
        const float* Bs = As + AF;
#pragma unroll
        for (int ks = 0; ks < 4; ++ks) {
            int k = ks * 8;
            uint32_t af[4][4], bf[8][2];
#pragma unroll
            for (int mt = 0; mt < 4; mt++) {
                int m = wm * 64 + mt * 16 + g;
                af[mt][0] = __float_as_uint(As[m * PADK + k + t]);
                af[mt][1] = __float_as_uint(As[(m + 8) * PADK + k + t]);
                af[mt][2] = __float_as_uint(As[m * PADK + k + t + 4]);
                af[mt][3] = __float_as_uint(As[(m + 8) * PADK + k + t + 4]);
            }
#pragma unroll
            for (int nt = 0; nt < 8; nt++) {
                int n = wn * 64 + nt * 8 + g;
                bf[nt][0] = __float_as_uint(Bs[n * PADK + k + t]);
                bf[nt][1] = __float_as_uint(Bs[n * PADK + k + t + 4]);
            }
#pragma unroll
            for (int mt = 0; mt < 4; mt++)
#pragma unroll
                for (int nt = 0; nt < 8; nt++)
                    mma8(acc[mt][nt], af[mt], bf[nt]);
        }
        __syncthreads();
    }

#pragma unroll
    for (int mt = 0; mt < 4; mt++) {
#pragma unroll
        for (int nt = 0; nt < 8; nt++) {
            int cg = c0 + wn * 64 + nt * 8 + 2 * t;
            float b0 = bias[cg], b1 = bias[cg + 1];
#pragma unroll
            for (int half = 0; half < 2; half++) {
                int rg = r0 + wm * 64 + mt * 16 + g + half * 8;
                float v0 = acc[mt][nt][half * 2 + 0] + b0;
                float v1 = acc[mt][nt][half * 2 + 1] + b1;
                float* dst;
                if (head_layout) {
                    int bb = rg >> 9, n = rg & 511;
                    int hh = cg >> 6, dk = cg & 63;
                    dst = outp + (((size_t)(bb * H + hh) * N + n) * DK) + dk;
                    *(float2*)dst = make_float2(to_tf32(v0), to_tf32(v1));
                } else {
                    dst = outp + (size_t)rg * D + cg;
                    *(float2*)dst = make_float2(v0, v1);
                }
            }
        }
    }
}

// ================ attention with mma.sync tf32 + fused distance bias ================
#define PADA 68
#define PADS 516
#define QS_OFF 0
#define KB0_OFF (64 * PADA)
#define KB1_OFF (2 * 64 * PADA)
#define SC_OFF  (3 * 64 * PADA)
#define LUT_OFF (SC_OFF + 64 * PADS)          // 441 floats
#define PK_OFF  (LUT_OFF + 448)               // 512 u16 => 256 floats
#define ATT_SMEM ((PK_OFF + 256) * 4)

__device__ __forceinline__ void load_chunk64(uint32_t dst_base, const float* src) {
    int tid = threadIdx.x;
#pragma unroll
    for (int it = 0; it < 4; ++it) {
        int idx = tid + it * 256;
        int row = idx >> 4, seg = idx & 15;
        CP_ASYNC16(dst_base + (uint32_t)(row * PADA + seg * 4) * 4, src + idx * 4);
    }
}

__global__ void __launch_bounds__(256, 1) attn_mma(const float* __restrict__ dist_emb,
                                                   float* __restrict__ att_out) {
    extern __shared__ float sm[];
    uint32_t smb = smem_u32(sm);
    float* Qs = sm + QS_OFF;
    float* Sc = sm + SC_OFF;
    float* lut = sm + LUT_OFF;
    unsigned short* pk = (unsigned short*)(sm + PK_OFF);

    int tid = threadIdx.x;
    int bh = blockIdx.y;
    int b = bh / H;
    int h = bh - b * H;
    int q0 = blockIdx.x * 64;

    const float* Qg = g_q + ((size_t)bh * N + q0) * DK;
    const float* Kg = g_k + (size_t)bh * N * DK;
    const float* Vg = g_v + (size_t)bh * N * DK;

    int lane = tid & 31, wid = tid >> 5;
    int wm = wid >> 2, wn = wid & 3;
    int g = lane >> 2, t = lane & 3;
    const float scale = 0.125f;

    // prologue: Q + K chunk 0
    load_chunk64(smb + QS_OFF * 4, Qg);
    load_chunk64(smb + KB0_OFF * 4, Kg);
    CP_COMMIT();

    // build distance-bias LUT (441 entries; grid-stride with 256 threads)
    for (int i = tid; i < 441; i += 256) {
        int dyc = i / 21 - 10, dxc = i % 21 - 10;
        int bin = (int)(sqrtf((float)(dxc * dxc + dyc * dyc)) * 2.0f);
        lut[i] = dist_emb[bin * H + h];
    }
    {
        int kk = tid * 2;
        if (kk < N) {
            pk[kk]     = (unsigned short)(g_py[b * N + kk] * 21 + g_px[b * N + kk]);
            pk[kk + 1] = (unsigned short)(g_py[b * N + kk + 1] * 21 + g_px[b * N + kk + 1]);
        }
    }

    // ---------- phase 1: S = Q K^T * scale ----------
    for (int kt = 0; kt < 8; ++kt) {
        if (kt < 7) {
            load_chunk64(smb + (((kt + 1) & 1) ? KB1_OFF : KB0_OFF) * 4, Kg + (kt + 1) * 4096);
            CP_COMMIT();
            CP_WAIT(1);
        } else {
            CP_WAIT(0);
        }
        __syncthreads();
        const float* Ks = sm + ((kt & 1) ? KB1_OFF : KB0_OFF);
        float acc[2][2][4];
#pragma unroll
        for (int i = 0; i < 2; i++)
#pragma unroll
            for (int j = 0; j < 2; j++)
#pragma unroll
                for (int r = 0; r < 4; r++) acc[i][j][r] = 0.f;
#pragma unroll
        for (int ks = 0; ks < 8; ++ks) {
            int k = ks * 8;
            uint32_t af[2][4], bf[2][2];
#pragma unroll
            for (int mt = 0; mt < 2; mt++) {
                int m = wm * 32 + mt * 16 + g;
                af[mt][0] = __float_as_uint(Qs[m * PADA + k + t]);
                af[mt][1] = __float_as_uint(Qs[(m + 8) * PADA + k + t]);
                af[mt][2] = __float_as_uint(Qs[m * PADA + k + t + 4]);
                af[mt][3] = __float_as_uint(Qs[(m + 8) * PADA + k + t + 4]);
            }
#pragma unroll
            for (int nt = 0; nt < 2; nt++) {
                int n = wn * 16 + nt * 8 + g;
                bf[nt][0] = __float_as_uint(Ks[n * PADA + k + t]);
                bf[nt][1] = __float_as_uint(Ks[n * PADA + k + t + 4]);
            }
#pragma unroll
            for (int mt = 0; mt < 2; mt++)
#pragma unroll
                for (int nt = 0; nt < 2; nt++)
                    mma8(acc[mt][nt], af[mt], bf[nt]);
        }
#pragma unroll
        for (int mt = 0; mt < 2; mt++) {
#pragma unroll
            for (int nt = 0; nt < 2; nt++) {
                int row = wm * 32 + mt * 16 + g;
                int col = kt * 64 + wn * 16 + nt * 8 + 2 * t;
                *(float2*)&Sc[row * PADS + col] =
                    make_float2(acc[mt][nt][0] * scale, acc[mt][nt][1] * scale);
                *(float2*)&Sc[(row + 8) * PADS + col] =
                    make_float2(acc[mt][nt][2] * scale, acc[mt][nt][3] * scale);
            }
        }
        __syncthreads();
    }

    // ---------- phase 2: softmax + LUT bias, write att, tf32 P into Sc ----------
#pragma unroll
    for (int rr = 0; rr < 8; rr++) {
        int qi = wid * 8 + rr;
        int qg = q0 + qi;
        int coff = 220 - (int)pk[qg];   // pk indexed by GLOBAL query id
        float* srow = Sc + qi * PADS;
        float m = -1e30f;
        for (int kk = lane; kk < N; kk += 32) {
            float s = srow[kk] + lut[(int)pk[kk] + coff];
            srow[kk] = s;
            m = fmaxf(m, s);
        }
#pragma unroll
        for (int o = 16; o; o >>= 1) m = fmaxf(m, __shfl_xor_sync(~0u, m, o));
        float ssum = 0.f;
        for (int kk = lane; kk < N; kk += 32) {
            float e = __expf(srow[kk] - m);
            srow[kk] = e;
            ssum += e;
        }
#pragma unroll
        for (int o = 16; o; o >>= 1) ssum += __shfl_xor_sync(~0u, ssum, o);
        float inv = 1.0f / ssum;
        float* arow = att_out + ((size_t)bh * N + qg) * N;
        for (int kk = lane; kk < N; kk += 32) {
            float p = srow[kk] * inv;
            arow[kk] = p;
            srow[kk] = to_tf32(p);
        }
    }

    // ---------- phase 3: O = P V ----------
    load_chunk64(smb + KB0_OFF * 4, Vg);
    CP_COMMIT();
    float oacc[2][2][4];
#pragma unroll
    for (int i = 0; i < 2; i++)
#pragma unroll
        for (int j = 0; j < 2; j++)
#pragma unroll
            for (int r = 0; r < 4; r++) oacc[i][j][r] = 0.f;

    for (int kt = 0; kt < 8; ++kt) {
        if (kt < 7) {
            load_chunk64(smb + (((kt + 1) & 1) ? KB1_OFF : KB0_OFF) * 4, Vg + (kt + 1) * 4096);
            CP_COMMIT();
            CP_WAIT(1);
        } else {
            CP_WAIT(0);
        }
        __syncthreads();
        const float* Vs = sm + ((kt & 1) ? KB1_OFF : KB0_OFF);
#pragma unroll
        for (int ks = 0; ks < 8; ++ks) {
            int k = ks * 8;
            uint32_t af[2][4], bf[2][2];
#pragma unroll
            for (int mt = 0; mt < 2; mt++) {
                int m = wm * 32 + mt * 16 + g;
                int sb = m * PADS + kt * 64 + k;
                af[mt][0] = __float_as_uint(Sc[sb + t]);
                af[mt][1] = __float_as_uint(Sc[sb + 8 * PADS + t]);
                af[mt][2] = __float_as_uint(Sc[sb + t + 4]);
                af[mt][3] = __float_as_uint(Sc[sb + 8 * PADS + t + 4]);
            }
#pragma unroll
            for (int nt = 0; nt < 2; nt++) {
                int n = wn * 16 + nt * 8 + g;
                bf[nt][0] = __float_as_uint(Vs[(k + t) * PADA + n]);
                bf[nt][1] = __float_as_uint(Vs[(k + t + 4) * PADA + n]);
            }
#pragma unroll
            for (int mt = 0; mt < 2; mt++)
#pragma unroll
                for (int nt = 0; nt < 2; nt++)
                    mma8(oacc[mt][nt], af[mt], bf[nt]);
        }
        __syncthreads();
    }

#pragma unroll
    for (int mt = 0; mt < 2; mt++) {
#pragma unroll
        for (int nt = 0; nt < 2; nt++) {
            int dk = wn * 16 + nt * 8 + 2 * t;
#pragma unroll
            for (int half = 0; half < 2; half++) {
                int qg = q0 + wm * 32 + mt * 16 + g + half * 8;
                float* dst = g_ao + ((size_t)(b * N + qg)) * D + h * DK + dk;
                *(float2*)dst = make_float2(to_tf32(oacc[mt][nt][half * 2 + 0]),
                                            to_tf32(oacc[mt][nt][half * 2 + 1]));
            }
        }
    }
}

// ---------------- launch ----------------
extern "C" void kernel_launch(void* const* d_in, const int* in_sizes, int n_in,
                              void* d_out, int out_size) {
    const float* features = (const float*)d_in[0];
    const float* boxes    = (const float*)d_in[1];
    const int*   iszs     = (const int*)  d_in[2];
    const float* Wq = (const float*)d_in[3];
    const float* bq = (const float*)d_in[4];
    const float* Wk = (const float*)d_in[5];
    const float* bk = (const float*)d_in[6];
    const float* Wv = (const float*)d_in[7];
    const float* bv = (const float*)d_in[8];
    const float* Wo = (const float*)d_in[9];
    const float* bo = (const float*)d_in[10];
    const float* gamma = (const float*)d_in[11];
    const float* beta  = (const float*)d_in[12];
    const float* dist_emb = (const float*)d_in[13];

    float* out = (float*)d_out;
    float* att = ((size_t)out_size >= OUT_ELEMS + ATT_ELEMS) ? out + OUT_ELEMS : out;

    cudaFuncSetAttribute(attn_mma, cudaFuncAttributeMaxDynamicSharedMemorySize, ATT_SMEM);
    cudaFuncSetAttribute(gemm_mma, cudaFuncAttributeMaxDynamicSharedMemorySize, GEMM_SMEM);

    float *gx, *gq, *gk, *gv, *gao;
    cudaGetSymbolAddress((void**)&gx, g_x);
    cudaGetSymbolAddress((void**)&gq, g_q);
    cudaGetSymbolAddress((void**)&gk, g_k);
    cudaGetSymbolAddress((void**)&gv, g_v);
    cudaGetSymbolAddress((void**)&gao, g_ao);

    ln_kernel<<<ROWS, 256>>>(features, gamma, beta);
    cvt_w<<<dim3((D * D) / 256, 4), 256>>>(Wq, Wk, Wv, Wo);
    patch_kernel<<<(ROWS + 255) / 256, 256>>>(boxes, iszs);

    dim3 gq3(D / BN, ROWS / BM, 3);
    gemm_mma<<<gq3, 256, GEMM_SMEM>>>(gx, bq, gq, bk, gk, bv, gv, 0, 1);

    dim3 ga(N / 64, B * H);
    attn_mma<<<ga, 256, ATT_SMEM>>>(dist_emb, att);

    dim3 go3(D / BN, ROWS / BM, 1);
    gemm_mma<<<go3, 256, GEMM_SMEM>>>(gao, bo, out, bo, out, bo, out, 3, 0);
}